// round 3
// baseline (speedup 1.0000x reference)
#include <cuda_runtime.h>
#include <math.h>

// PhaseMoE: v[b,:] = sum_k p_hat[b,k] * (silu(silu(x W1k + b1k) W2k + b2k) W3k + b3k)
// x = concat(u[256], cond[1024], tau[1])  -> 1281
// B=32768, K=8, HID=128, LATENT=256
//
// Fully fused: one CTA handles 32 tokens, loops over all 8 experts, all
// intermediates live in shared memory / registers. FFMA-bound baseline.

#define TB 32   // tokens per block

__global__ __launch_bounds__(256, 2)
void phase_moe_kernel(const float* __restrict__ cond,
                      const float* __restrict__ u,
                      const float* __restrict__ tau,
                      const float* __restrict__ p_hat,
                      const float* __restrict__ W1,
                      const float* __restrict__ b1,
                      const float* __restrict__ W2,
                      const float* __restrict__ b2,
                      const float* __restrict__ W3,
                      const float* __restrict__ b3,
                      float* __restrict__ out)
{
    // 48 KB static smem total (fits default limit, no attribute needed):
    __shared__ float wbuf[32 * 128];   // 16 KB weight tile; layer3 views as [16][256]
    __shared__ float h1s[TB][128];     // 16 KB
    __shared__ float h2s[TB][128];     // 16 KB; first 1024 floats double as xs[32][32]

    float* xs = &h2s[0][0];            // alias: xs dead before h2s is written

    const int t  = threadIdx.x;
    const int ti = t >> 5;             // 0..7
    const int tj = t & 31;             // 0..31
    const int b0 = blockIdx.x * TB;
    const int r0 = ti * 4;             // this thread's row base (4 rows)

    // Output accumulator: rows r0..r0+3, cols tj*8..tj*8+7
    float vacc[32];
#pragma unroll
    for (int i = 0; i < 32; ++i) vacc[i] = 0.f;

    for (int k = 0; k < 8; ++k) {
        //================= layer 1: h1 = silu(x @ W1k + b1k), x: 32 x 1281 =====
        float acc[16];  // rows r0+r, cols tj*4+c
#pragma unroll
        for (int c = 0; c < 4; ++c) {
            float bv = b1[k * 128 + tj * 4 + c];
#pragma unroll
            for (int r = 0; r < 4; ++r) acc[r * 4 + c] = bv;
        }
        const float* W1k = W1 + (size_t)k * 1281 * 128;

        for (int kc0 = 0; kc0 < 1281; kc0 += 32) {
            __syncthreads();  // prior smem reads (and h2s/xs reuse) complete
            // ---- stage xs[32][32] (zero-fill past 1281) ----
#pragma unroll
            for (int q = 0; q < 4; ++q) {
                int idx = t + q * 256;
                int row = idx >> 5;
                int kk  = idx & 31;
                int g   = kc0 + kk;
                float v = 0.f;
                if (g < 1281) {
                    int gb = b0 + row;
                    if (g < 256)        v = u[gb * 256 + g];
                    else if (g < 1280)  v = cond[gb * 1024 + (g - 256)];
                    else                v = tau[gb];
                }
                xs[row * 32 + kk] = v;
            }
            // ---- stage wbuf[32][128] via float4 (zero-fill past 1281) ----
#pragma unroll
            for (int q = 0; q < 4; ++q) {
                int f  = t + q * 256;   // float4 index, 1024 total
                int kk = f >> 5;        // 32 float4 per 128-wide row
                int c4 = f & 31;
                int g  = kc0 + kk;
                float4 v = make_float4(0.f, 0.f, 0.f, 0.f);
                if (g < 1281)
                    v = *reinterpret_cast<const float4*>(&W1k[g * 128 + c4 * 4]);
                *reinterpret_cast<float4*>(&wbuf[kk * 128 + c4 * 4]) = v;
            }
            __syncthreads();
            // ---- 32x128 += 32x32 @ 32x128 ----
#pragma unroll
            for (int kk = 0; kk < 32; ++kk) {
                float4 bw = *reinterpret_cast<const float4*>(&wbuf[kk * 128 + tj * 4]);
#pragma unroll
                for (int r = 0; r < 4; ++r) {
                    float a = xs[(r0 + r) * 32 + kk];   // warp-broadcast
                    acc[r * 4 + 0] = fmaf(a, bw.x, acc[r * 4 + 0]);
                    acc[r * 4 + 1] = fmaf(a, bw.y, acc[r * 4 + 1]);
                    acc[r * 4 + 2] = fmaf(a, bw.z, acc[r * 4 + 2]);
                    acc[r * 4 + 3] = fmaf(a, bw.w, acc[r * 4 + 3]);
                }
            }
        }
        // silu -> h1s (own elements; layer2's first sync orders the reads)
#pragma unroll
        for (int r = 0; r < 4; ++r)
#pragma unroll
            for (int c = 0; c < 4; ++c) {
                float x = acc[r * 4 + c];
                h1s[r0 + r][tj * 4 + c] = x / (1.f + __expf(-x));
            }

        //================= layer 2: h2 = silu(h1 @ W2k + b2k), 128 -> 128 =====
#pragma unroll
        for (int c = 0; c < 4; ++c) {
            float bv = b2[k * 128 + tj * 4 + c];
#pragma unroll
            for (int r = 0; r < 4; ++r) acc[r * 4 + c] = bv;
        }
        const float* W2k = W2 + (size_t)k * 128 * 128;
        for (int kc0 = 0; kc0 < 128; kc0 += 32) {
            __syncthreads();
#pragma unroll
            for (int q = 0; q < 4; ++q) {
                int f  = t + q * 256;
                int kk = f >> 5;
                int c4 = f & 31;
                *reinterpret_cast<float4*>(&wbuf[kk * 128 + c4 * 4]) =
                    *reinterpret_cast<const float4*>(&W2k[(kc0 + kk) * 128 + c4 * 4]);
            }
            __syncthreads();
#pragma unroll
            for (int kk = 0; kk < 32; ++kk) {
                float4 bw = *reinterpret_cast<const float4*>(&wbuf[kk * 128 + tj * 4]);
#pragma unroll
                for (int r = 0; r < 4; ++r) {
                    float a = h1s[r0 + r][kc0 + kk];
                    acc[r * 4 + 0] = fmaf(a, bw.x, acc[r * 4 + 0]);
                    acc[r * 4 + 1] = fmaf(a, bw.y, acc[r * 4 + 1]);
                    acc[r * 4 + 2] = fmaf(a, bw.z, acc[r * 4 + 2]);
                    acc[r * 4 + 3] = fmaf(a, bw.w, acc[r * 4 + 3]);
                }
            }
        }
        // silu -> h2s (xs alias is dead; own elements only)
#pragma unroll
        for (int r = 0; r < 4; ++r)
#pragma unroll
            for (int c = 0; c < 4; ++c) {
                float x = acc[r * 4 + c];
                h2s[r0 + r][tj * 4 + c] = x / (1.f + __expf(-x));
            }

        //================= layer 3: e3 = h2 @ W3k + b3k, 128 -> 256 ===========
        float e3[32];  // rows r0+r, cols tj*8+c
#pragma unroll
        for (int c = 0; c < 8; ++c) {
            float bv = b3[k * 256 + tj * 8 + c];
#pragma unroll
            for (int r = 0; r < 4; ++r) e3[r * 8 + c] = bv;
        }
        const float* W3k = W3 + (size_t)k * 128 * 256;
        for (int kc0 = 0; kc0 < 128; kc0 += 16) {
            __syncthreads();
            // wbuf viewed as [16][256]: 4096 floats = 1024 float4
#pragma unroll
            for (int q = 0; q < 4; ++q) {
                int f  = t + q * 256;
                int kk = f >> 6;        // 64 float4 per 256-wide row
                int c4 = f & 63;
                *reinterpret_cast<float4*>(&wbuf[kk * 256 + c4 * 4]) =
                    *reinterpret_cast<const float4*>(&W3k[(kc0 + kk) * 256 + c4 * 4]);
            }
            __syncthreads();
#pragma unroll
            for (int kk = 0; kk < 16; ++kk) {
                float4 bw0 = *reinterpret_cast<const float4*>(&wbuf[kk * 256 + tj * 8]);
                float4 bw1 = *reinterpret_cast<const float4*>(&wbuf[kk * 256 + tj * 8 + 4]);
#pragma unroll
                for (int r = 0; r < 4; ++r) {
                    float a = h2s[r0 + r][kc0 + kk];
                    e3[r * 8 + 0] = fmaf(a, bw0.x, e3[r * 8 + 0]);
                    e3[r * 8 + 1] = fmaf(a, bw0.y, e3[r * 8 + 1]);
                    e3[r * 8 + 2] = fmaf(a, bw0.z, e3[r * 8 + 2]);
                    e3[r * 8 + 3] = fmaf(a, bw0.w, e3[r * 8 + 3]);
                    e3[r * 8 + 4] = fmaf(a, bw1.x, e3[r * 8 + 4]);
                    e3[r * 8 + 5] = fmaf(a, bw1.y, e3[r * 8 + 5]);
                    e3[r * 8 + 6] = fmaf(a, bw1.z, e3[r * 8 + 6]);
                    e3[r * 8 + 7] = fmaf(a, bw1.w, e3[r * 8 + 7]);
                }
            }
        }
        // gate-weighted accumulate
#pragma unroll
        for (int r = 0; r < 4; ++r) {
            float p = p_hat[(size_t)(b0 + r0 + r) * 8 + k];
#pragma unroll
            for (int c = 0; c < 8; ++c)
                vacc[r * 8 + c] = fmaf(p, e3[r * 8 + c], vacc[r * 8 + c]);
        }
    }  // experts

    // epilogue: vectorized stores
#pragma unroll
    for (int r = 0; r < 4; ++r) {
        float4 o0 = make_float4(vacc[r * 8 + 0], vacc[r * 8 + 1],
                                vacc[r * 8 + 2], vacc[r * 8 + 3]);
        float4 o1 = make_float4(vacc[r * 8 + 4], vacc[r * 8 + 5],
                                vacc[r * 8 + 6], vacc[r * 8 + 7]);
        float* orow = out + (size_t)(b0 + r0 + r) * 256 + tj * 8;
        *reinterpret_cast<float4*>(orow)     = o0;
        *reinterpret_cast<float4*>(orow + 4) = o1;
    }
}

extern "C" void kernel_launch(void* const* d_in, const int* in_sizes, int n_in,
                              void* d_out, int out_size) {
    const float* cond = (const float*)d_in[0];
    const float* u    = (const float*)d_in[1];
    const float* tau  = (const float*)d_in[2];
    const float* p    = (const float*)d_in[3];
    const float* W1   = (const float*)d_in[4];
    const float* b1   = (const float*)d_in[5];
    const float* W2   = (const float*)d_in[6];
    const float* b2   = (const float*)d_in[7];
    const float* W3   = (const float*)d_in[8];
    const float* b3   = (const float*)d_in[9];
    float* out = (float*)d_out;

    phase_moe_kernel<<<32768 / TB, 256>>>(cond, u, tau, p,
                                          W1, b1, W2, b2, W3, b3, out);
}

// round 4
// speedup vs baseline: 1.0048x; 1.0048x over previous
#include <cuda_runtime.h>
#include <math.h>

// PhaseMoE: v[b,:] = sum_k p_hat[b,k] * (silu(silu(x W1k + b1k) W2k + b2k) W3k + b3k)
// x = concat(u[256], cond[1024], tau[1])  -> 1281
// B=32768, K=8, HID=128, LATENT=256
//
// Fully fused: one CTA handles 32 tokens, loops over all 8 experts, all
// intermediates live in shared memory / registers. FFMA-bound baseline.

#define TB 32   // tokens per block

__global__ __launch_bounds__(256, 2)
void phase_moe_kernel(const float* __restrict__ cond,
                      const float* __restrict__ u,
                      const float* __restrict__ tau,
                      const float* __restrict__ p_hat,
                      const float* __restrict__ W1,
                      const float* __restrict__ b1,
                      const float* __restrict__ W2,
                      const float* __restrict__ b2,
                      const float* __restrict__ W3,
                      const float* __restrict__ b3,
                      float* __restrict__ out)
{
    // 48 KB static smem total (fits default limit, no attribute needed):
    __shared__ float wbuf[32 * 128];   // 16 KB weight tile; layer3 views as [16][256]
    __shared__ float h1s[TB][128];     // 16 KB
    __shared__ float h2s[TB][128];     // 16 KB; first 1024 floats double as xs[32][32]

    float* xs = &h2s[0][0];            // alias: xs dead before h2s is written

    const int t  = threadIdx.x;
    const int ti = t >> 5;             // 0..7
    const int tj = t & 31;             // 0..31
    const int b0 = blockIdx.x * TB;
    const int r0 = ti * 4;             // this thread's row base (4 rows)

    // Output accumulator: rows r0..r0+3, cols tj*8..tj*8+7
    float vacc[32];
#pragma unroll
    for (int i = 0; i < 32; ++i) vacc[i] = 0.f;

    for (int k = 0; k < 8; ++k) {
        //================= layer 1: h1 = silu(x @ W1k + b1k), x: 32 x 1281 =====
        float acc[16];  // rows r0+r, cols tj*4+c
#pragma unroll
        for (int c = 0; c < 4; ++c) {
            float bv = b1[k * 128 + tj * 4 + c];
#pragma unroll
            for (int r = 0; r < 4; ++r) acc[r * 4 + c] = bv;
        }
        const float* W1k = W1 + (size_t)k * 1281 * 128;

        for (int kc0 = 0; kc0 < 1281; kc0 += 32) {
            __syncthreads();  // prior smem reads (and h2s/xs reuse) complete
            // ---- stage xs[32][32] (zero-fill past 1281) ----
#pragma unroll
            for (int q = 0; q < 4; ++q) {
                int idx = t + q * 256;
                int row = idx >> 5;
                int kk  = idx & 31;
                int g   = kc0 + kk;
                float v = 0.f;
                if (g < 1281) {
                    int gb = b0 + row;
                    if (g < 256)        v = u[gb * 256 + g];
                    else if (g < 1280)  v = cond[gb * 1024 + (g - 256)];
                    else                v = tau[gb];
                }
                xs[row * 32 + kk] = v;
            }
            // ---- stage wbuf[32][128] via float4 (zero-fill past 1281) ----
#pragma unroll
            for (int q = 0; q < 4; ++q) {
                int f  = t + q * 256;   // float4 index, 1024 total
                int kk = f >> 5;        // 32 float4 per 128-wide row
                int c4 = f & 31;
                int g  = kc0 + kk;
                float4 v = make_float4(0.f, 0.f, 0.f, 0.f);
                if (g < 1281)
                    v = *reinterpret_cast<const float4*>(&W1k[g * 128 + c4 * 4]);
                *reinterpret_cast<float4*>(&wbuf[kk * 128 + c4 * 4]) = v;
            }
            __syncthreads();
            // ---- 32x128 += 32x32 @ 32x128 ----
#pragma unroll
            for (int kk = 0; kk < 32; ++kk) {
                float4 bw = *reinterpret_cast<const float4*>(&wbuf[kk * 128 + tj * 4]);
#pragma unroll
                for (int r = 0; r < 4; ++r) {
                    float a = xs[(r0 + r) * 32 + kk];   // warp-broadcast
                    acc[r * 4 + 0] = fmaf(a, bw.x, acc[r * 4 + 0]);
                    acc[r * 4 + 1] = fmaf(a, bw.y, acc[r * 4 + 1]);
                    acc[r * 4 + 2] = fmaf(a, bw.z, acc[r * 4 + 2]);
                    acc[r * 4 + 3] = fmaf(a, bw.w, acc[r * 4 + 3]);
                }
            }
        }
        // silu -> h1s (own elements; layer2's first sync orders the reads)
#pragma unroll
        for (int r = 0; r < 4; ++r)
#pragma unroll
            for (int c = 0; c < 4; ++c) {
                float x = acc[r * 4 + c];
                h1s[r0 + r][tj * 4 + c] = x / (1.f + __expf(-x));
            }

        //================= layer 2: h2 = silu(h1 @ W2k + b2k), 128 -> 128 =====
#pragma unroll
        for (int c = 0; c < 4; ++c) {
            float bv = b2[k * 128 + tj * 4 + c];
#pragma unroll
            for (int r = 0; r < 4; ++r) acc[r * 4 + c] = bv;
        }
        const float* W2k = W2 + (size_t)k * 128 * 128;
        for (int kc0 = 0; kc0 < 128; kc0 += 32) {
            __syncthreads();
#pragma unroll
            for (int q = 0; q < 4; ++q) {
                int f  = t + q * 256;
                int kk = f >> 5;
                int c4 = f & 31;
                *reinterpret_cast<float4*>(&wbuf[kk * 128 + c4 * 4]) =
                    *reinterpret_cast<const float4*>(&W2k[(kc0 + kk) * 128 + c4 * 4]);
            }
            __syncthreads();
#pragma unroll
            for (int kk = 0; kk < 32; ++kk) {
                float4 bw = *reinterpret_cast<const float4*>(&wbuf[kk * 128 + tj * 4]);
#pragma unroll
                for (int r = 0; r < 4; ++r) {
                    float a = h1s[r0 + r][kc0 + kk];
                    acc[r * 4 + 0] = fmaf(a, bw.x, acc[r * 4 + 0]);
                    acc[r * 4 + 1] = fmaf(a, bw.y, acc[r * 4 + 1]);
                    acc[r * 4 + 2] = fmaf(a, bw.z, acc[r * 4 + 2]);
                    acc[r * 4 + 3] = fmaf(a, bw.w, acc[r * 4 + 3]);
                }
            }
        }
        // silu -> h2s (xs alias is dead; own elements only)
#pragma unroll
        for (int r = 0; r < 4; ++r)
#pragma unroll
            for (int c = 0; c < 4; ++c) {
                float x = acc[r * 4 + c];
                h2s[r0 + r][tj * 4 + c] = x / (1.f + __expf(-x));
            }

        //================= layer 3: e3 = h2 @ W3k + b3k, 128 -> 256 ===========
        float e3[32];  // rows r0+r, cols tj*8+c
#pragma unroll
        for (int c = 0; c < 8; ++c) {
            float bv = b3[k * 256 + tj * 8 + c];
#pragma unroll
            for (int r = 0; r < 4; ++r) e3[r * 8 + c] = bv;
        }
        const float* W3k = W3 + (size_t)k * 128 * 256;
        for (int kc0 = 0; kc0 < 128; kc0 += 16) {
            __syncthreads();
            // wbuf viewed as [16][256]: 4096 floats = 1024 float4
#pragma unroll
            for (int q = 0; q < 4; ++q) {
                int f  = t + q * 256;
                int kk = f >> 6;        // 64 float4 per 256-wide row
                int c4 = f & 63;
                *reinterpret_cast<float4*>(&wbuf[kk * 256 + c4 * 4]) =
                    *reinterpret_cast<const float4*>(&W3k[(kc0 + kk) * 256 + c4 * 4]);
            }
            __syncthreads();
#pragma unroll
            for (int kk = 0; kk < 16; ++kk) {
                float4 bw0 = *reinterpret_cast<const float4*>(&wbuf[kk * 256 + tj * 8]);
                float4 bw1 = *reinterpret_cast<const float4*>(&wbuf[kk * 256 + tj * 8 + 4]);
#pragma unroll
                for (int r = 0; r < 4; ++r) {
                    float a = h2s[r0 + r][kc0 + kk];
                    e3[r * 8 + 0] = fmaf(a, bw0.x, e3[r * 8 + 0]);
                    e3[r * 8 + 1] = fmaf(a, bw0.y, e3[r * 8 + 1]);
                    e3[r * 8 + 2] = fmaf(a, bw0.z, e3[r * 8 + 2]);
                    e3[r * 8 + 3] = fmaf(a, bw0.w, e3[r * 8 + 3]);
                    e3[r * 8 + 4] = fmaf(a, bw1.x, e3[r * 8 + 4]);
                    e3[r * 8 + 5] = fmaf(a, bw1.y, e3[r * 8 + 5]);
                    e3[r * 8 + 6] = fmaf(a, bw1.z, e3[r * 8 + 6]);
                    e3[r * 8 + 7] = fmaf(a, bw1.w, e3[r * 8 + 7]);
                }
            }
        }
        // gate-weighted accumulate
#pragma unroll
        for (int r = 0; r < 4; ++r) {
            float p = p_hat[(size_t)(b0 + r0 + r) * 8 + k];
#pragma unroll
            for (int c = 0; c < 8; ++c)
                vacc[r * 8 + c] = fmaf(p, e3[r * 8 + c], vacc[r * 8 + c]);
        }
    }  // experts

    // epilogue: vectorized stores
#pragma unroll
    for (int r = 0; r < 4; ++r) {
        float4 o0 = make_float4(vacc[r * 8 + 0], vacc[r * 8 + 1],
                                vacc[r * 8 + 2], vacc[r * 8 + 3]);
        float4 o1 = make_float4(vacc[r * 8 + 4], vacc[r * 8 + 5],
                                vacc[r * 8 + 6], vacc[r * 8 + 7]);
        float* orow = out + (size_t)(b0 + r0 + r) * 256 + tj * 8;
        *reinterpret_cast<float4*>(orow)     = o0;
        *reinterpret_cast<float4*>(orow + 4) = o1;
    }
}

extern "C" void kernel_launch(void* const* d_in, const int* in_sizes, int n_in,
                              void* d_out, int out_size) {
    const float* cond = (const float*)d_in[0];
    const float* u    = (const float*)d_in[1];
    const float* tau  = (const float*)d_in[2];
    const float* p    = (const float*)d_in[3];
    const float* W1   = (const float*)d_in[4];
    const float* b1   = (const float*)d_in[5];
    const float* W2   = (const float*)d_in[6];
    const float* b2   = (const float*)d_in[7];
    const float* W3   = (const float*)d_in[8];
    const float* b3   = (const float*)d_in[9];
    float* out = (float*)d_out;

    phase_moe_kernel<<<32768 / TB, 256>>>(cond, u, tau, p,
                                          W1, b1, W2, b2, W3, b3, out);
}